// round 3
// baseline (speedup 1.0000x reference)
#include <cuda_runtime.h>
#include <cuda_bf16.h>
#include <cstdint>

#define NV 40962
#define KR 19
#define NC 64            // C_in == C_out == 64
#define NBATCH 4
#define TILE_M 128
#define TILES_PER_B 321  // ceil(40962/128)
#define NTILES (NBATCH * TILES_PER_B)

// -------- device scratch (allocation-free rule: __device__ globals) --------
__device__ __align__(1024) __nv_bfloat16 g_xt_hi[(size_t)NBATCH * NV * NC]; // ~21 MB
__device__ __align__(1024) __nv_bfloat16 g_xt_lo[(size_t)NBATCH * NV * NC]; // ~21 MB
__device__ __align__(1024) __nv_bfloat16 g_w_hi[KR * NC * NC];              // 152 KB
__device__ __align__(1024) __nv_bfloat16 g_w_lo[KR * NC * NC];

// ---------------------------- helpers ----------------------------------
__device__ __forceinline__ uint32_t smem_to_u32(const void* p) {
    uint32_t a;
    asm("{ .reg .u64 t; cvta.to.shared.u64 t, %1; cvt.u32.u64 %0, t; }"
        : "=r"(a) : "l"(p));
    return a;
}

#define SWZ(off) ((off) ^ (((off) >> 3) & 0x70))

__device__ __forceinline__ void cp16(uint32_t saddr, const void* gaddr) {
    asm volatile("cp.async.cg.shared.global [%0], [%1], 16;"
                 :: "r"(saddr), "l"(gaddr) : "memory");
}
__device__ __forceinline__ void cp_commit() {
    asm volatile("cp.async.commit_group;" ::: "memory");
}
__device__ __forceinline__ void cp_wait1() {
    asm volatile("cp.async.wait_group 1;" ::: "memory");
}

__device__ __forceinline__ void ldsm_x4(uint32_t& r0, uint32_t& r1, uint32_t& r2,
                                        uint32_t& r3, uint32_t a) {
    asm volatile("ldmatrix.sync.aligned.m8n8.x4.shared.b16 {%0,%1,%2,%3}, [%4];"
                 : "=r"(r0), "=r"(r1), "=r"(r2), "=r"(r3) : "r"(a));
}

__device__ __forceinline__ void mma_bf16(float* c, uint32_t a0, uint32_t a1,
                                         uint32_t a2, uint32_t a3,
                                         uint32_t b0, uint32_t b1) {
    asm volatile(
        "mma.sync.aligned.m16n8k16.row.col.f32.bf16.bf16.f32 "
        "{%0,%1,%2,%3}, {%4,%5,%6,%7}, {%8,%9}, {%0,%1,%2,%3};"
        : "+f"(c[0]), "+f"(c[1]), "+f"(c[2]), "+f"(c[3])
        : "r"(a0), "r"(a1), "r"(a2), "r"(a3), "r"(b0), "r"(b1));
}

// ------------------------------ prep kernels --------------------------------
// W[o][19*64] -> chunk-major bf16 hi/lo: g_w_*[k][o][c]
__global__ void prep_w_kernel(const float* __restrict__ W) {
    int i = blockIdx.x * blockDim.x + threadIdx.x;
    if (i >= NC * KR * NC) return;
    int o = i / (KR * NC);
    int kk = i % (KR * NC);
    int k = kk >> 6, c = kk & 63;
    float w = W[i];
    __nv_bfloat16 hi = __float2bfloat16(w);
    float lo = w - __bfloat162float(hi);
    g_w_hi[((size_t)k * NC + o) * NC + c] = hi;
    g_w_lo[((size_t)k * NC + o) * NC + c] = __float2bfloat16(lo);
}

// Transpose x[b][c][v] -> xt[b][v][c], split bf16 hi/lo.
__global__ void prep_x_kernel(const float* __restrict__ x) {
    __shared__ float s[64][65];
    int b = blockIdx.y;
    int v0 = blockIdx.x * 64;
    int tid = threadIdx.x;  // 256
    for (int i = tid; i < 64 * 64; i += 256) {
        int c = i >> 6, vi = i & 63;
        int v = v0 + vi;
        s[c][vi] = (v < NV) ? x[((size_t)b * NC + c) * NV + v] : 0.f;
    }
    __syncthreads();
    for (int i = tid; i < 64 * 64; i += 256) {
        int vi = i >> 6, c = i & 63;
        int v = v0 + vi;
        if (v < NV) {
            float val = s[c][vi];
            __nv_bfloat16 hi = __float2bfloat16(val);
            float lo = val - __bfloat162float(hi);
            size_t off = ((size_t)b * NV + v) * NC + c;
            g_xt_hi[off] = hi;
            g_xt_lo[off] = __float2bfloat16(lo);
        }
    }
}

// ------------------------------ main kernel ---------------------------------
// smem layout (bytes):
#define OFF_IDX   0          // 128*19*4 = 9728
#define OFF_BIAS  9728       // 64 floats
#define OFF_AHI0  10240      // 128 rows x 128B (SW128) = 16 KB
#define OFF_ALO0  26624
#define OFF_WHI0  43008      // 64 rows x 128B = 8 KB
#define OFF_WLO0  51200
#define OFF_AHI1  59392
#define OFF_ALO1  75776
#define OFF_WHI1  92160
#define OFF_WLO1  100352
#define SMEM_TOTAL 108544
#define STAGE_STRIDE (OFF_AHI1 - OFF_AHI0)   // 49152

__global__ __launch_bounds__(256, 2) void conv_main(const int* __restrict__ neigh,
                                                    const float* __restrict__ bias,
                                                    float* __restrict__ out) {
    extern __shared__ char smem[];
    uint32_t sb = smem_to_u32(smem);
    const int tid = threadIdx.x;
    const int wid = tid >> 5, lid = tid & 31;
    const int b = blockIdx.x / TILES_PER_B;
    const int t = blockIdx.x % TILES_PER_B;
    const int vbase = t * TILE_M;
    int rows = NV - vbase; if (rows > TILE_M) rows = TILE_M;

    if (tid < NC) ((float*)(smem + OFF_BIAS))[tid] = bias[tid];

    // neighbor indices -> smem
    int* s_idx = (int*)(smem + OFF_IDX);
    {
        int tot = rows * KR;
        const int* src = neigh + (size_t)vbase * KR;
        for (int i = tid; i < tot; i += 256) s_idx[i] = src[i];
    }
    __syncthreads();

    const __nv_bfloat16* xh = g_xt_hi + (size_t)b * NV * NC;
    const __nv_bfloat16* xl = g_xt_lo + (size_t)b * NV * NC;

    // ---- gather issue for one chunk into a stage ----
    const int seg = tid & 7;          // 16B segment in a 128B row
    const int r0g = tid >> 3;         // 0..31
    auto issue_chunk = [&](int k, int stage) {
        uint32_t base = sb + OFF_AHI0 + stage * STAGE_STRIDE;
        uint32_t baseLo = base + (OFF_ALO0 - OFF_AHI0);
        #pragma unroll
        for (int j = 0; j < 4; j++) {
            int r = r0g + j * 32;
            int rr = (r < rows) ? r : 0;
            int v = s_idx[rr * KR + k];
            const char* gh = (const char*)(xh + (size_t)v * NC) + seg * 16;
            const char* gl = (const char*)(xl + (size_t)v * NC) + seg * 16;
            uint32_t sw = SWZ((uint32_t)(r * 128 + seg * 16));
            cp16(base + sw, gh);
            cp16(baseLo + sw, gl);
        }
        uint32_t wb = sb + OFF_WHI0 + stage * STAGE_STRIDE;
        uint32_t wbLo = wb + (OFF_WLO0 - OFF_WHI0);
        const char* wh = (const char*)(g_w_hi + (size_t)k * NC * NC);
        const char* wl = (const char*)(g_w_lo + (size_t)k * NC * NC);
        #pragma unroll
        for (int j = 0; j < 2; j++) {
            int r = r0g + j * 32;   // 0..63
            uint32_t sw = SWZ((uint32_t)(r * 128 + seg * 16));
            cp16(wb + sw, wh + r * 128 + seg * 16);
            cp16(wbLo + sw, wl + r * 128 + seg * 16);
        }
        cp_commit();
    };

    // ---- warp tiling: 4 M-warps x 2 N-warps; warp tile 32x32 ----
    const int wm = wid & 3;        // M block
    const int wn = wid >> 2;       // N block
    float acc[2][4][4];
    #pragma unroll
    for (int mt = 0; mt < 2; mt++)
        #pragma unroll
        for (int nt = 0; nt < 4; nt++)
            #pragma unroll
            for (int i = 0; i < 4; i++) acc[mt][nt][i] = 0.f;

    // per-lane ldmatrix row components (byte offsets, pre-swizzle)
    // A: lanes 0-7: rows+0..7@c0; 8-15: +8..15@c0; 16-23: 0..7@c0+8; 24-31: 8..15@c0+8
    const uint32_t aRow = (uint32_t)(wm * 32 + (lid & 7) + 8 * ((lid >> 3) & 1)) << 7;
    const uint32_t aColLane = (uint32_t)(lid >> 4) << 4;       // +16B for k upper half
    // B: lanes 0-7: n0..7@k0; 8-15: n0..7@k8; 16-23: n0+8..15@k0; 24-31: n0+8..15@k8
    const uint32_t bRow = (uint32_t)(wn * 32 + (lid & 7) + 8 * (lid >> 4)) << 7;
    const uint32_t bColLane = (uint32_t)((lid >> 3) & 1) << 4;

    issue_chunk(0, 0);

    for (int k = 0; k < KR; k++) {
        if (k + 1 < KR) issue_chunk(k + 1, (k + 1) & 1);
        else cp_commit();           // empty group keeps wait_group 1 arithmetic uniform
        cp_wait1();
        __syncthreads();

        const int stage = k & 1;
        const uint32_t aHi = sb + OFF_AHI0 + stage * STAGE_STRIDE;
        const uint32_t aLo = aHi + (OFF_ALO0 - OFF_AHI0);
        const uint32_t bHi = sb + OFF_WHI0 + stage * STAGE_STRIDE;
        const uint32_t bLo = bHi + (OFF_WLO0 - OFF_WHI0);

        #pragma unroll
        for (int kk = 0; kk < 4; kk++) {
            const uint32_t kb = (uint32_t)(kk * 32);
            // A fragments (2 m16 tiles) hi & lo
            uint32_t Ah[2][4], Al[2][4];
            #pragma unroll
            for (int mt = 0; mt < 2; mt++) {
                uint32_t off = aRow + ((uint32_t)mt << 11) + kb + aColLane;
                uint32_t sw = SWZ(off);
                ldsm_x4(Ah[mt][0], Ah[mt][1], Ah[mt][2], Ah[mt][3], aHi + sw);
                ldsm_x4(Al[mt][0], Al[mt][1], Al[mt][2], Al[mt][3], aLo + sw);
            }
            // B fragments (4 n8 tiles via 2 x4 loads) hi & lo
            uint32_t Bh[8], Bl[8];
            #pragma unroll
            for (int p = 0; p < 2; p++) {
                uint32_t off = bRow + ((uint32_t)p << 11) + kb + bColLane;
                uint32_t sw = SWZ(off);
                ldsm_x4(Bh[p * 4 + 0], Bh[p * 4 + 1], Bh[p * 4 + 2], Bh[p * 4 + 3], bHi + sw);
                ldsm_x4(Bl[p * 4 + 0], Bl[p * 4 + 1], Bl[p * 4 + 2], Bl[p * 4 + 3], bLo + sw);
            }
            #pragma unroll
            for (int mt = 0; mt < 2; mt++)
                #pragma unroll
                for (int nt = 0; nt < 4; nt++) {
                    uint32_t b0h = Bh[nt * 2], b1h = Bh[nt * 2 + 1];
                    mma_bf16(acc[mt][nt], Ah[mt][0], Ah[mt][1], Ah[mt][2], Ah[mt][3], b0h, b1h);
                    mma_bf16(acc[mt][nt], Al[mt][0], Al[mt][1], Al[mt][2], Al[mt][3], b0h, b1h);
                    mma_bf16(acc[mt][nt], Ah[mt][0], Ah[mt][1], Ah[mt][2], Ah[mt][3],
                             Bl[nt * 2], Bl[nt * 2 + 1]);
                }
        }
        __syncthreads();
    }

    // ---- epilogue: stage through smem for coalesced [o][v] stores ----
    float* s_out = (float*)(smem + OFF_AHI0);   // 32 KB, reuse stage-0 A buffers
    #pragma unroll
    for (int mt = 0; mt < 2; mt++) {
        int r = wm * 32 + mt * 16 + (lid >> 2);
        #pragma unroll
        for (int nt = 0; nt < 4; nt++) {
            int o = wn * 32 + nt * 8 + (lid & 3) * 2;
            s_out[(o + 0) * 128 + r]     = acc[mt][nt][0];
            s_out[(o + 1) * 128 + r]     = acc[mt][nt][1];
            s_out[(o + 0) * 128 + r + 8] = acc[mt][nt][2];
            s_out[(o + 1) * 128 + r + 8] = acc[mt][nt][3];
        }
    }
    __syncthreads();

    const float* bs = (const float*)(smem + OFF_BIAS);
    float* ob = out + (size_t)b * NC * NV + vbase;
    #pragma unroll
    for (int i = 0; i < 32; i++) {
        int idx = tid + i * 256;
        int o = idx >> 7, v = idx & 127;
        if (v < rows) ob[(size_t)o * NV + v] = s_out[idx] + bs[o];
    }
}

// ------------------------------ launch --------------------------------------
extern "C" void kernel_launch(void* const* d_in, const int* in_sizes, int n_in,
                              void* d_out, int out_size) {
    const float* x     = (const float*)d_in[0];
    const int*   neigh = (const int*)d_in[1];
    const float* W     = (const float*)d_in[2];
    const float* bias  = (const float*)d_in[3];
    float* out = (float*)d_out;

    cudaFuncSetAttribute(conv_main, cudaFuncAttributeMaxDynamicSharedMemorySize, SMEM_TOTAL);

    prep_w_kernel<<<(NC * KR * NC + 255) / 256, 256>>>(W);
    prep_x_kernel<<<dim3((NV + 63) / 64, NBATCH), 256>>>(x);
    conv_main<<<NTILES, 256, SMEM_TOTAL>>>(neigh, bias, out);
}